// round 6
// baseline (speedup 1.0000x reference)
#include <cuda_runtime.h>
#include <cuda_fp16.h>
#include <cstdint>

// Problem constants
#define NN 50000
#define FF 64
#define HH 128

// ---------------- device scratch (static globals, no cudaMalloc) -------------
__device__ float g_deg[NN];
__device__ float g_dinv[NN];
__device__ float g_AX[(size_t)NN * FF];          // aggregated X  (N x 64)
__device__ float g_ZR[(size_t)NN * 256];         // Z cols 0..127, R cols 128..255
// pre-permuted fp16 weights (fragment order):
//  6 gate blocks of 6144 uint32 (64 cols x 192 k) + 1 Lout block of 4096 (64 x 128)
__device__ uint32_t g_Bp[6 * 6144 + 4096];
__device__ float g_bcat[384];                    // packed gate biases

// ---------------- helpers -----------------------------------------------------
__device__ __forceinline__ uint32_t f2h2(float lo, float hi) {
    __half2 h = __floats2half2_rn(lo, hi);
    return *(uint32_t*)&h;
}
__device__ __forceinline__ void mma_f16(float* c, const uint32_t* a, const uint32_t* b) {
    asm volatile(
        "mma.sync.aligned.m16n8k16.row.col.f32.f16.f16.f32 "
        "{%0,%1,%2,%3}, {%4,%5,%6,%7}, {%8,%9}, {%0,%1,%2,%3};"
        : "+f"(c[0]), "+f"(c[1]), "+f"(c[2]), "+f"(c[3])
        : "r"(a[0]), "r"(a[1]), "r"(a[2]), "r"(a[3]), "r"(b[0]), "r"(b[1]));
}

// ---------------- weight fold (W_g @ Lg_top) + bias fold ----------------------
// One block per gate. W (64x128) cached in smem; L read coalesced.
__global__ void __launch_bounds__(256) k_fold(
    const float* Wz, const float* bz, const float* Wr, const float* br,
    const float* Wh, const float* bh,
    const float* Lz, const float* Lzb, const float* Lr, const float* Lrb,
    const float* Lh, const float* Lhb) {
    __shared__ float sW[64 * 128];
    __shared__ float sb[128];
    const int g = blockIdx.x;
    const float* W  = (g == 0) ? Wz : (g == 1) ? Wr : Wh;
    const float* L  = (g == 0) ? Lz : (g == 1) ? Lr : Lh;
    const float* bg = (g == 0) ? bz : (g == 1) ? br : bh;
    const float* Lb = (g == 0) ? Lzb : (g == 1) ? Lrb : Lhb;
    const int t = threadIdx.x;
    for (int i = t; i < 64 * 128; i += 256) sW[i] = W[i];
    if (t < 128) sb[t] = bg[t];
    __syncthreads();

    const int jj = t & 127;
    const int kh = t >> 7;     // 0/1 -> k rows [32kh, 32kh+32)
    float acc[32];
    #pragma unroll
    for (int i = 0; i < 32; i++) acc[i] = 0.f;
    float bacc = 0.f;
    for (int tt = 0; tt < 128; tt++) {
        float l = L[tt * 128 + jj];
        if (kh == 0) bacc += sb[tt] * l;
        #pragma unroll
        for (int ki = 0; ki < 32; ki++) acc[ki] += sW[(kh * 32 + ki) * 128 + tt] * l;
    }
    if (kh == 0) g_bcat[g * 128 + jj] = Lb[jj] + bacc;

    const int blk = g * 2 + (jj >> 6);
    const int cc  = (jj >> 3) & 7;
    const int gid = jj & 7;
    #pragma unroll
    for (int m = 0; m < 16; m++) {
        int k = kh * 32 + 2 * m;
        int ks = k >> 4, jh = (k >> 3) & 1, tig = (k >> 1) & 3;
        int lane = gid * 4 + tig;
        g_Bp[blk * 6144 + ((ks * 8 + cc) * 32 + lane) * 2 + jh] =
            f2h2(acc[2 * m], acc[2 * m + 1]);
    }
}

// ---------------- copy-only packing (gate bottom halves + Lout) ---------------
__global__ void k_pack2(const float* Lz, const float* Lr, const float* Lh,
                        const float* LoW) {
    int idx = blockIdx.x * blockDim.x + threadIdx.x;
    const int TG = 6 * 4096;
    if (idx < TG) {
        int blk = idx >> 12;
        int r   = idx & 4095;
        int jh   = r & 1;
        int lane = (r >> 1) & 31;
        int cc   = (r >> 6) & 7;
        int ks   = (r >> 9) + 4;      // 4..11
        int n  = blk * 64 + cc * 8 + (lane >> 2);
        int k0 = ks * 16 + jh * 8 + (lane & 3) * 2;   // 64..190
        int g = n >> 7;
        int jj = n & 127;
        const float* L = (g == 0) ? Lz : (g == 1) ? Lr : Lh;
        float v0 = L[(64 + k0) * 128 + jj];
        float v1 = L[(64 + k0 + 1) * 128 + jj];
        g_Bp[blk * 6144 + 2048 + r] = f2h2(v0, v1);
    } else if (idx < TG + 4096) {
        int r = idx - TG;
        int jh   = r & 1;
        int lane = (r >> 1) & 31;
        int cc   = (r >> 6) & 7;
        int ks   = r >> 9;            // 0..7
        int n  = cc * 8 + (lane >> 2);
        int k0 = ks * 16 + jh * 8 + (lane & 3) * 2;
        g_Bp[6 * 6144 + r] = f2h2(LoW[k0 * 64 + n], LoW[(k0 + 1) * 64 + n]);
    }
}

// ---------------- degree / normalization -------------------------------------
__global__ void k_deg(const int* ei, const float* ew, int E) {
    int e = blockIdx.x * blockDim.x + threadIdx.x;
    if (e < E) atomicAdd(&g_deg[ei[E + e]], ew[e]);
}

// fused: dinv = rsqrt(deg+1), reset deg (for next graph replay), AX self-loop init
__global__ void k_dinvax(const float* __restrict__ X) {
    int tid = blockIdx.x * blockDim.x + threadIdx.x;
    if (tid >= NN * 16) return;
    int i = tid >> 4, q = tid & 15;
    float d  = g_deg[i] + 1.0f;       // self-loop weight 1
    float di = rsqrtf(d);
    __syncwarp();
    if (q == 0) { g_dinv[i] = di; g_deg[i] = 0.f; }
    float s = di * di;
    float4 x = reinterpret_cast<const float4*>(X + (size_t)i * 64)[q];
    float4 v = make_float4(x.x * s, x.y * s, x.z * s, x.w * s);
    reinterpret_cast<float4*>(g_AX + (size_t)i * 64)[q] = v;
}

// Edge scatter: AX[dst] += dinv[src]*w*dinv[dst] * X[src]   (16 threads/edge)
__global__ void k_agg(const int* __restrict__ ei, const float* __restrict__ ew,
                      const float* __restrict__ X, int E) {
    int tid = blockIdx.x * blockDim.x + threadIdx.x;
    int e = tid >> 4;
    if (e >= E) return;
    int q = tid & 15;
    int s = ei[e];
    int d = ei[E + e];
    float norm = g_dinv[s] * ew[e] * g_dinv[d];
    float4 x = reinterpret_cast<const float4*>(X + (size_t)s * 64)[q];
    float* p = g_AX + (size_t)d * 64 + q * 4;
    asm volatile("red.global.add.v4.f32 [%0], {%1, %2, %3, %4};"
                 :: "l"(p), "f"(x.x * norm), "f"(x.y * norm),
                    "f"(x.z * norm), "f"(x.w * norm)
                 : "memory");
}

// ---------------- GEMM1: [AX|Hs] @ W1 -> sigmoid -> Z,R -----------------------
// Block tile 128 x 128 (grid.y=2 for 256 cols), 8 warps, warp tile 32 x 64.
#define STR2 20     // half2 units per A smem row

__global__ void __launch_bounds__(256, 2)
gemm1(const float* __restrict__ A1,
      const float* __restrict__ Hs,
      const uint32_t* __restrict__ Bp,
      const float* __restrict__ bias,
      float* __restrict__ out0) {
    extern __shared__ uint32_t sm[];
    uint32_t* As2 = sm;             // 128*STR2
    uint32_t* Bs  = sm + 128 * STR2; // 12288 (two 64-col blocks)

    const int t    = threadIdx.x;
    const int lane = t & 31;
    const int wid  = t >> 5;
    const int gid  = lane >> 2;
    const int tig  = lane & 3;
    const int warpRow = wid & 3;
    const int warpCol = wid >> 2;
    const int blockRow = blockIdx.x * 128;
    const int colGrp   = blockIdx.y * 128;

    {
        const uint4* src = (const uint4*)(Bp + (size_t)blockIdx.y * 12288);
        uint4* dst = (uint4*)Bs;
        #pragma unroll
        for (int i = 0; i < 12; i++) dst[t + i * 256] = src[t + i * 256];
    }

    float acc[2][8][4];
    #pragma unroll
    for (int mi = 0; mi < 2; mi++)
        #pragma unroll
        for (int ni = 0; ni < 8; ni++)
            #pragma unroll
            for (int c = 0; c < 4; c++) acc[mi][ni][c] = 0.f;

    for (int k0 = 0; k0 < 192; k0 += 32) {
        #pragma unroll
        for (int it = 0; it < 4; it++) {
            int i = t + it * 256;
            int row = i >> 3;
            int q   = i & 7;
            int kg  = k0 + q * 4;
            int grow = blockRow + row;
            float4 v = make_float4(0.f, 0.f, 0.f, 0.f);
            if (grow < NN) {
                if (kg < 64) v = *(const float4*)(A1 + (size_t)grow * 64 + kg);
                else         v = *(const float4*)(Hs + (size_t)grow * 128 + (kg - 64));
            }
            As2[row * STR2 + q * 2]     = f2h2(v.x, v.y);
            As2[row * STR2 + q * 2 + 1] = f2h2(v.z, v.w);
        }
        __syncthreads();
        #pragma unroll
        for (int s = 0; s < 2; s++) {
            const int ksg = (k0 >> 4) + s;
            uint32_t a[2][4];
            #pragma unroll
            for (int mi = 0; mi < 2; mi++) {
                int r0 = warpRow * 32 + mi * 16 + gid;
                a[mi][0] = As2[r0 * STR2 + s * 8 + tig];
                a[mi][1] = As2[(r0 + 8) * STR2 + s * 8 + tig];
                a[mi][2] = As2[r0 * STR2 + s * 8 + tig + 4];
                a[mi][3] = As2[(r0 + 8) * STR2 + s * 8 + tig + 4];
            }
            #pragma unroll
            for (int ni = 0; ni < 8; ni++) {
                uint2 bv = *(const uint2*)&Bs[warpCol * 6144 + ((ksg * 8 + ni) * 32 + lane) * 2];
                uint32_t b[2] = {bv.x, bv.y};
                mma_f16(acc[0][ni], a[0], b);
                mma_f16(acc[1][ni], a[1], b);
            }
        }
        __syncthreads();
    }

    #pragma unroll
    for (int mi = 0; mi < 2; mi++)
        #pragma unroll
        for (int half = 0; half < 2; half++) {
            int row = blockRow + warpRow * 32 + mi * 16 + gid + half * 8;
            if (row >= NN) continue;
            #pragma unroll
            for (int ni = 0; ni < 8; ni++) {
                int col  = warpCol * 64 + ni * 8 + tig * 2;
                int gcol = colGrp + col;
                float v0 = acc[mi][ni][half * 2]     + bias[gcol];
                float v1 = acc[mi][ni][half * 2 + 1] + bias[gcol + 1];
                *(float2*)(out0 + (size_t)row * 256 + gcol) =
                    make_float2(1.f / (1.f + expf(-v0)), 1.f / (1.f + expf(-v1)));
            }
        }
}

// ---------------- GEMM2+3 fused: GRU update + output linear -------------------
// Stage 1: [AX | Hs*R] @ W2 (128x192 @ 192x128) -> tanh -> h, relu(h)->smem fp16
// Stage 2: relu(h) @ Lout (128x128 @ 128x64) -> y
#define RSTR 68     // half2 units per reluh smem row

__global__ void __launch_bounds__(256, 2)
gemm23(const float* __restrict__ A1,
       const float* __restrict__ Hs,
       const float* __restrict__ ZR,
       const uint32_t* __restrict__ Bp2,
       const uint32_t* __restrict__ Bp3,
       const float* __restrict__ biash,
       const float* __restrict__ LoB,
       float* __restrict__ out_h,
       float* __restrict__ out_y) {
    extern __shared__ uint32_t sm[];
    uint32_t* As2 = sm;                      // 2560
    uint32_t* Bs2 = sm + 2560;               // 12288
    uint32_t* Bs3 = Bs2 + 12288;             // 4096
    uint32_t* RS  = Bs3 + 4096;              // 128*RSTR = 8704

    const int t    = threadIdx.x;
    const int lane = t & 31;
    const int wid  = t >> 5;
    const int gid  = lane >> 2;
    const int tig  = lane & 3;
    const int warpRow = wid & 3;
    const int warpCol = wid >> 2;
    const int blockRow = blockIdx.x * 128;

    {
        const uint4* src = (const uint4*)Bp2;
        uint4* dst = (uint4*)Bs2;
        #pragma unroll
        for (int i = 0; i < 12; i++) dst[t + i * 256] = src[t + i * 256];
        const uint4* src3 = (const uint4*)Bp3;
        uint4* dst3 = (uint4*)Bs3;
        #pragma unroll
        for (int i = 0; i < 4; i++) dst3[t + i * 256] = src3[t + i * 256];
    }

    float acc[2][8][4];
    #pragma unroll
    for (int mi = 0; mi < 2; mi++)
        #pragma unroll
        for (int ni = 0; ni < 8; ni++)
            #pragma unroll
            for (int c = 0; c < 4; c++) acc[mi][ni][c] = 0.f;

    for (int k0 = 0; k0 < 192; k0 += 32) {
        #pragma unroll
        for (int it = 0; it < 4; it++) {
            int i = t + it * 256;
            int row = i >> 3;
            int q   = i & 7;
            int kg  = k0 + q * 4;
            int grow = blockRow + row;
            float4 v = make_float4(0.f, 0.f, 0.f, 0.f);
            if (grow < NN) {
                if (kg < 64) {
                    v = *(const float4*)(A1 + (size_t)grow * 64 + kg);
                } else {
                    int k2 = kg - 64;
                    v = *(const float4*)(Hs + (size_t)grow * 128 + k2);
                    float4 r = *(const float4*)(ZR + (size_t)grow * 256 + 128 + k2);
                    v.x *= r.x; v.y *= r.y; v.z *= r.z; v.w *= r.w;
                }
            }
            As2[row * STR2 + q * 2]     = f2h2(v.x, v.y);
            As2[row * STR2 + q * 2 + 1] = f2h2(v.z, v.w);
        }
        __syncthreads();
        #pragma unroll
        for (int s = 0; s < 2; s++) {
            const int ksg = (k0 >> 4) + s;
            uint32_t a[2][4];
            #pragma unroll
            for (int mi = 0; mi < 2; mi++) {
                int r0 = warpRow * 32 + mi * 16 + gid;
                a[mi][0] = As2[r0 * STR2 + s * 8 + tig];
                a[mi][1] = As2[(r0 + 8) * STR2 + s * 8 + tig];
                a[mi][2] = As2[r0 * STR2 + s * 8 + tig + 4];
                a[mi][3] = As2[(r0 + 8) * STR2 + s * 8 + tig + 4];
            }
            #pragma unroll
            for (int ni = 0; ni < 8; ni++) {
                uint2 bv = *(const uint2*)&Bs2[warpCol * 6144 + ((ksg * 8 + ni) * 32 + lane) * 2];
                uint32_t b[2] = {bv.x, bv.y};
                mma_f16(acc[0][ni], a[0], b);
                mma_f16(acc[1][ni], a[1], b);
            }
        }
        __syncthreads();
    }

    // ---- epilogue 1: GRU update -> h (gmem) + relu(h) (smem fp16, A-frag) ----
    #pragma unroll
    for (int mi = 0; mi < 2; mi++)
        #pragma unroll
        for (int half = 0; half < 2; half++) {
            int lrow = warpRow * 32 + mi * 16 + gid + half * 8;
            int row = blockRow + lrow;
            #pragma unroll
            for (int ni = 0; ni < 8; ni++) {
                int col = warpCol * 64 + ni * 8 + tig * 2;
                float h0 = 0.f, h1 = 0.f;
                if (row < NN) {
                    float v0 = acc[mi][ni][half * 2]     + biash[col];
                    float v1 = acc[mi][ni][half * 2 + 1] + biash[col + 1];
                    float2 z  = *(const float2*)(ZR + (size_t)row * 256 + col);
                    float2 hs = *(const float2*)(Hs + (size_t)row * 128 + col);
                    h0 = z.x * hs.x + (1.f - z.x) * tanhf(v0);
                    h1 = z.y * hs.y + (1.f - z.y) * tanhf(v1);
                    *(float2*)(out_h + (size_t)row * 128 + col) = make_float2(h0, h1);
                }
                RS[lrow * RSTR + (col >> 1)] = f2h2(fmaxf(h0, 0.f), fmaxf(h1, 0.f));
            }
        }
    __syncthreads();

    // ---- stage 2: relu(h) @ Lout, warp tile 32 x 32 ----
    float acc2[2][4][4];
    #pragma unroll
    for (int mi = 0; mi < 2; mi++)
        #pragma unroll
        for (int ni = 0; ni < 4; ni++)
            #pragma unroll
            for (int c = 0; c < 4; c++) acc2[mi][ni][c] = 0.f;

    #pragma unroll
    for (int ksg = 0; ksg < 8; ksg++) {
        uint32_t a[2][4];
        #pragma unroll
        for (int mi = 0; mi < 2; mi++) {
            int r0 = warpRow * 32 + mi * 16 + gid;
            a[mi][0] = RS[r0 * RSTR + ksg * 8 + tig];
            a[mi][1] = RS[(r0 + 8) * RSTR + ksg * 8 + tig];
            a[mi][2] = RS[r0 * RSTR + ksg * 8 + tig + 4];
            a[mi][3] = RS[(r0 + 8) * RSTR + ksg * 8 + tig + 4];
        }
        #pragma unroll
        for (int ni = 0; ni < 4; ni++) {
            int c = warpCol * 4 + ni;
            uint2 bv = *(const uint2*)&Bs3[((ksg * 8 + c) * 32 + lane) * 2];
            uint32_t b[2] = {bv.x, bv.y};
            mma_f16(acc2[0][ni], a[0], b);
            mma_f16(acc2[1][ni], a[1], b);
        }
    }

    // ---- epilogue 2: y ----
    #pragma unroll
    for (int mi = 0; mi < 2; mi++)
        #pragma unroll
        for (int half = 0; half < 2; half++) {
            int row = blockRow + warpRow * 32 + mi * 16 + gid + half * 8;
            if (row >= NN) continue;
            #pragma unroll
            for (int ni = 0; ni < 4; ni++) {
                int col = warpCol * 32 + ni * 8 + tig * 2;
                float v0 = acc2[mi][ni][half * 2]     + LoB[col];
                float v1 = acc2[mi][ni][half * 2 + 1] + LoB[col + 1];
                *(float2*)(out_y + (size_t)row * 64 + col) = make_float2(v0, v1);
            }
        }
}

// ---------------- launch ------------------------------------------------------
extern "C" void kernel_launch(void* const* d_in, const int* in_sizes, int n_in,
                              void* d_out, int out_size) {
    const int*   ei  = (const int*)d_in[0];
    const float* X   = (const float*)d_in[1];
    const float* ew  = (const float*)d_in[2];
    const float* Hs  = (const float*)d_in[3];
    const float* Wz  = (const float*)d_in[4];
    const float* bz  = (const float*)d_in[5];
    const float* Wr  = (const float*)d_in[6];
    const float* br  = (const float*)d_in[7];
    const float* Wh  = (const float*)d_in[8];
    const float* bh  = (const float*)d_in[9];
    const float* Lz  = (const float*)d_in[10];
    const float* Lzb = (const float*)d_in[11];
    const float* Lr  = (const float*)d_in[12];
    const float* Lrb = (const float*)d_in[13];
    const float* Lh  = (const float*)d_in[14];
    const float* Lhb = (const float*)d_in[15];
    const float* LoW = (const float*)d_in[16];
    const float* LoB = (const float*)d_in[17];

    const int E = in_sizes[2];

    float* out   = (float*)d_out;
    float* out_y = out;                       // N x 64
    float* out_h = out + (size_t)NN * FF;     // N x 128

    void *pAX, *pZR, *pBp, *pBcat;
    cudaGetSymbolAddress(&pAX, g_AX);
    cudaGetSymbolAddress(&pZR, g_ZR);
    cudaGetSymbolAddress(&pBp, g_Bp);
    cudaGetSymbolAddress(&pBcat, g_bcat);

    const int sm1  = (128 * STR2 + 12288) * 4;                  // 59392
    const int sm23 = (2560 + 12288 + 4096 + 128 * RSTR) * 4;    // 110592
    cudaFuncSetAttribute(gemm1,  cudaFuncAttributeMaxDynamicSharedMemorySize, sm1);
    cudaFuncSetAttribute(gemm23, cudaFuncAttributeMaxDynamicSharedMemorySize, sm23);

    // 1. weight fold + packing
    k_fold<<<3, 256>>>(Wz, bz, Wr, br, Wh, bh, Lz, Lzb, Lr, Lrb, Lh, Lhb);
    k_pack2<<<(6 * 4096 + 4096 + 255) / 256, 256>>>(Lz, Lr, Lh, LoW);
    // 2. degree
    k_deg<<<(E + 255) / 256, 256>>>(ei, ew, E);
    // 3. dinv + AX self-loop init (+ deg reset for next replay)
    k_dinvax<<<(NN * 16 + 255) / 256, 256>>>(X);
    // 4. aggregate X once (GCN linearity)
    k_agg<<<(E * 16 + 255) / 256, 256>>>(ei, ew, X, E);

    const int gridM = (NN + 127) / 128;  // 391

    // 5. GEMM1: [AX | Hs] @ W1 -> sigmoid -> Z,R  (256 cols = 2 col-blocks)
    gemm1<<<dim3(gridM, 2), 256, sm1>>>(
        (const float*)pAX, Hs, (const uint32_t*)pBp,
        (const float*)pBcat, (float*)pZR);
    // 6. GEMM2+3 fused: GRU update -> h, then relu(h) @ Lout -> y
    gemm23<<<dim3(gridM, 1), 256, sm23>>>(
        (const float*)pAX, Hs, (const float*)pZR,
        (const uint32_t*)pBp + 4 * 6144, (const uint32_t*)pBp + 6 * 6144,
        (const float*)pBcat + 256, LoB, out_h, out_y);
}